// round 15
// baseline (speedup 1.0000x reference)
#include <cuda_runtime.h>
#include <cuda_fp16.h>
#include <math.h>

#define N_NODES  100000
#define N_EDGES  1600000
#define N_GRAPHS 512
#define F_IN     20
#define HID      128
#define OUT_F    64
#define NBLK_SCAN ((N_NODES + 1023) / 1024)   // 98

// ---------------- static device scratch (no runtime allocation) ----------------
__device__ int    g_cnt[N_NODES];     // zero-init; re-zeroed by scan1_k each run
__device__ int    g_fill[N_NODES];    // zero-init; re-zeroed by scan1_k each run
__device__ int    g_rowptr[N_NODES + 1];
__device__ float  g_dinv[N_NODES];
__device__ int2   g_cw[N_EDGES];            // {src, w as float bits}
__device__ __align__(16) __half g_hx32[(size_t)N_NODES * 32];   // layer-1 agg, fp16 K=32 padded
__device__ __align__(16) __half g_hA[(size_t)N_NODES * HID];    // fp16 activations
__device__ __align__(16) __half g_hagg[(size_t)N_NODES * HID];  // fp16 aggregate (GEMM A)
__device__ uint2  g_hWp[2][8 * 128 * 4];    // W2/W3 fp16 B-frag layout (32KB each)
__device__ uint2  g_hWp1[2 * 128 * 4];      // W1 fp16 B-frag layout (K=32 padded)
__device__ int    g_gstart[N_GRAPHS + 1];
__device__ int    g_bsum[NBLK_SCAN];

// ---------------- CSR build ----------------
__global__ void hist_k(const int* __restrict__ ei) {
    int e = blockIdx.x * blockDim.x + threadIdx.x;
    if (e < N_EDGES) {
        int d = ei[N_EDGES + e];
        atomicAdd(&g_cnt[d], 1);
    }
}

// pass 1: per-block exclusive scan + block sums; also dinv; re-zeroes cnt/fill
__global__ __launch_bounds__(1024) void scan1_k() {
    __shared__ int wsum[32];
    int tid = threadIdx.x, lane = tid & 31, wid = tid >> 5;
    int i = blockIdx.x * 1024 + tid;
    int v = 0;
    if (i < N_NODES) {
        v = g_cnt[i];
        g_cnt[i] = 0;                    // ready for next replay
        g_fill[i] = 0;                   // ready for fill_k
        g_dinv[i] = rsqrtf((float)(v + 1));   // +1 self loop
    }
    int xv = v;
#pragma unroll
    for (int d = 1; d < 32; d <<= 1) {
        int t = __shfl_up_sync(0xffffffffu, xv, d);
        if (lane >= d) xv += t;
    }
    if (lane == 31) wsum[wid] = xv;
    __syncthreads();
    if (wid == 0) {
        int y = wsum[lane];
#pragma unroll
        for (int d = 1; d < 32; d <<= 1) {
            int t = __shfl_up_sync(0xffffffffu, y, d);
            if (lane >= d) y += t;
        }
        wsum[lane] = y;
    }
    __syncthreads();
    int incl = xv + (wid > 0 ? wsum[wid - 1] : 0);
    if (i < N_NODES) g_rowptr[i] = incl - v;
    if (tid == 1023) g_bsum[blockIdx.x] = incl;
}

// pass 2+3 fused (+ graph bounds): each block reduces block sums, adds offset
__global__ __launch_bounds__(1024) void scan23_k(const int* __restrict__ batch) {
    __shared__ unsigned long long red[32];
    int tid = threadIdx.x, lane = tid & 31, wid = tid >> 5;
    int v = (tid < NBLK_SCAN) ? g_bsum[tid] : 0;
    int vp = (tid < (int)blockIdx.x) ? v : 0;
    unsigned long long p = ((unsigned long long)(unsigned)v << 32) | (unsigned)vp;
#pragma unroll
    for (int d = 16; d > 0; d >>= 1)
        p += __shfl_down_sync(0xffffffffu, p, d);
    if (lane == 0) red[wid] = p;
    __syncthreads();
    if (wid == 0) {
        unsigned long long q = red[lane];
#pragma unroll
        for (int d = 16; d > 0; d >>= 1)
            q += __shfl_down_sync(0xffffffffu, q, d);
        if (lane == 0) red[0] = q;
    }
    __syncthreads();
    int offset = (int)(red[0] & 0xffffffffull);
    int total  = (int)(red[0] >> 32);
    int i = blockIdx.x * 1024 + tid;
    if (i < N_NODES) g_rowptr[i] += offset;
    if (blockIdx.x == NBLK_SCAN - 1 && tid == 0) g_rowptr[N_NODES] = total;

    // graph segment bounds from sorted batch
    if (i < N_NODES) {
        int b = batch[i];
        if (i == 0) {
            for (int g = 0; g <= b; g++) g_gstart[g] = 0;
        }
        int bn = (i + 1 < N_NODES) ? batch[i + 1] : N_GRAPHS;
        for (int g = b + 1; g <= bn; g++) g_gstart[g] = i + 1;
    }
}

__global__ void fill_k(const int* __restrict__ ei) {
    int e = blockIdx.x * blockDim.x + threadIdx.x;
    if (e < N_EDGES) {
        int s = ei[e];
        int d = ei[N_EDGES + e];
        int p = g_rowptr[d] + atomicAdd(&g_fill[d], 1);
        int2 cw;
        cw.x = s;
        cw.y = __float_as_int(g_dinv[s]);
        g_cw[p] = cw;
    }
}

// ---- pack all weights into fp16 B-fragment layouts (one kernel) ----
__global__ __launch_bounds__(256) void packAll_k(const float* __restrict__ W1,
                                                 const float* __restrict__ W2,
                                                 const float* __restrict__ W3) {
    int idx = blockIdx.x * 256 + threadIdx.x;
    if (idx < 8192) {
        const float* W = (idx < 4096) ? W2 : W3;
        int slot = idx >> 12;
        int l = idx & 4095;
        int tig = l & 3;
        int n   = (l >> 2) & 127;
        int kt  = l >> 9;
        int k0  = kt * 16 + 2 * tig;
        __half2 lo = __floats2half2_rn(W[(k0 + 0) * HID + n], W[(k0 + 1) * HID + n]);
        __half2 hi = __floats2half2_rn(W[(k0 + 8) * HID + n], W[(k0 + 9) * HID + n]);
        uint2 u;
        u.x = *(unsigned*)&lo;
        u.y = *(unsigned*)&hi;
        g_hWp[slot][l] = u;
    } else if (idx < 8192 + 1024) {
        int l = idx - 8192;
        int tig = l & 3;
        int n   = (l >> 2) & 127;
        int kt  = l >> 9;
        int k0  = kt * 16 + 2 * tig;
        float w0 = (k0 + 0 < F_IN) ? W1[(k0 + 0) * HID + n] : 0.f;
        float w1 = (k0 + 1 < F_IN) ? W1[(k0 + 1) * HID + n] : 0.f;
        float w2 = (k0 + 8 < F_IN) ? W1[(k0 + 8) * HID + n] : 0.f;
        float w3 = (k0 + 9 < F_IN) ? W1[(k0 + 9) * HID + n] : 0.f;
        __half2 lo = __floats2half2_rn(w0, w1);
        __half2 hi = __floats2half2_rn(w2, w3);
        uint2 u;
        u.x = *(unsigned*)&lo;
        u.y = *(unsigned*)&hi;
        g_hWp1[l] = u;
    }
}

// ---------------- layer-1 aggregation: x fp32 -> g_hx32 fp16 [N,32] ----------------
// warp per node; edge loop unrolled x4 for MLP
__global__ __launch_bounds__(256) void agg20_k(const float* __restrict__ x) {
    int warp = (blockIdx.x * blockDim.x + threadIdx.x) >> 5;
    int lane = threadIdx.x & 31;
    if (warp >= N_NODES) return;
    int beg = g_rowptr[warp], end = g_rowptr[warp + 1];
    float di = g_dinv[warp];
    float acc = 0.0f;
    if (lane < F_IN) acc = di * x[(size_t)warp * F_IN + lane];
    int e = beg;
    for (; e + 3 < end; e += 4) {
        int2 c0 = g_cw[e], c1 = g_cw[e + 1], c2 = g_cw[e + 2], c3 = g_cw[e + 3];
        float v0 = 0.f, v1 = 0.f, v2 = 0.f, v3 = 0.f;
        if (lane < F_IN) {
            v0 = x[(size_t)c0.x * F_IN + lane];
            v1 = x[(size_t)c1.x * F_IN + lane];
            v2 = x[(size_t)c2.x * F_IN + lane];
            v3 = x[(size_t)c3.x * F_IN + lane];
        }
        acc = fmaf(__int_as_float(c0.y), v0, acc);
        acc = fmaf(__int_as_float(c1.y), v1, acc);
        acc = fmaf(__int_as_float(c2.y), v2, acc);
        acc = fmaf(__int_as_float(c3.y), v3, acc);
    }
    for (; e < end; e++) {
        int2 cw = g_cw[e];
        if (lane < F_IN)
            acc = fmaf(__int_as_float(cw.y), x[(size_t)cw.x * F_IN + lane], acc);
    }
    g_hx32[(size_t)warp * 32 + lane] = __float2half_rn(lane < F_IN ? di * acc : 0.0f);
}

// ---------------- fp16-gather aggregation: g_hA -> g_hagg ----------------
// TWO nodes per warp: half-warp (16 lanes) per node, uint4 (16B, 8ch) per lane.
#define ACC8(U, W) { \
    float2 f0 = __half22float2(*(const __half2*)&(U).x); \
    float2 f1 = __half22float2(*(const __half2*)&(U).y); \
    float2 f2 = __half22float2(*(const __half2*)&(U).z); \
    float2 f3 = __half22float2(*(const __half2*)&(U).w); \
    acc[0] = fmaf((W), f0.x, acc[0]); acc[1] = fmaf((W), f0.y, acc[1]); \
    acc[2] = fmaf((W), f1.x, acc[2]); acc[3] = fmaf((W), f1.y, acc[3]); \
    acc[4] = fmaf((W), f2.x, acc[4]); acc[5] = fmaf((W), f2.y, acc[5]); \
    acc[6] = fmaf((W), f3.x, acc[6]); acc[7] = fmaf((W), f3.y, acc[7]); }

__global__ __launch_bounds__(256) void agg128h_k() {
    int warp = (blockIdx.x * blockDim.x + threadIdx.x) >> 5;
    int lane = threadIdx.x & 31;
    int half = lane >> 4, hl = lane & 15;
    int node = warp * 2 + half;
    if (node >= N_NODES) return;
    const uint4* H16 = (const uint4*)g_hA;   // 16 x 16B per node row
    int beg = g_rowptr[node], end = g_rowptr[node + 1];
    float di = g_dinv[node];

    float acc[8];
    {   // self loop
        uint4 u = H16[(size_t)node * 16 + hl];
        float2 f0 = __half22float2(*(const __half2*)&u.x);
        float2 f1 = __half22float2(*(const __half2*)&u.y);
        float2 f2 = __half22float2(*(const __half2*)&u.z);
        float2 f3 = __half22float2(*(const __half2*)&u.w);
        acc[0] = di * f0.x; acc[1] = di * f0.y;
        acc[2] = di * f1.x; acc[3] = di * f1.y;
        acc[4] = di * f2.x; acc[5] = di * f2.y;
        acc[6] = di * f3.x; acc[7] = di * f3.y;
    }

    int e = beg;
    for (; e + 3 < end; e += 4) {
        int2 c0 = g_cw[e], c1 = g_cw[e + 1], c2 = g_cw[e + 2], c3 = g_cw[e + 3];
        uint4 u0 = H16[(size_t)c0.x * 16 + hl];
        uint4 u1 = H16[(size_t)c1.x * 16 + hl];
        uint4 u2 = H16[(size_t)c2.x * 16 + hl];
        uint4 u3 = H16[(size_t)c3.x * 16 + hl];
        ACC8(u0, __int_as_float(c0.y))
        ACC8(u1, __int_as_float(c1.y))
        ACC8(u2, __int_as_float(c2.y))
        ACC8(u3, __int_as_float(c3.y))
    }
    for (; e < end; e++) {
        int2 cw = g_cw[e];
        uint4 u = H16[(size_t)cw.x * 16 + hl];
        ACC8(u, __int_as_float(cw.y))
    }

    uint4 o;
    __half2 h0 = __floats2half2_rn(di * acc[0], di * acc[1]);
    __half2 h1 = __floats2half2_rn(di * acc[2], di * acc[3]);
    __half2 h2 = __floats2half2_rn(di * acc[4], di * acc[5]);
    __half2 h3 = __floats2half2_rn(di * acc[6], di * acc[7]);
    o.x = *(unsigned*)&h0; o.y = *(unsigned*)&h1;
    o.z = *(unsigned*)&h2; o.w = *(unsigned*)&h3;
    ((uint4*)g_hagg)[(size_t)node * 16 + hl] = o;
}

// ---- fp16 MMA GEMM, K=32: g_hx32[N,32] @ g_hWp1 + bias, relu -> g_hA ----
__global__ __launch_bounds__(128) void gemm32_h(const float* __restrict__ bias) {
    __shared__ __half sA[64 * 40];             // pitch 40 halves (80B)
    int tid = threadIdx.x, lane = tid & 31, wid = tid >> 5;
    int base = blockIdx.x * 64;

    const uint4* A16 = (const uint4*)g_hx32;   // 4 x 8-half chunks per node
    for (int i = tid; i < 64 * 4; i += 128) {
        int row = i >> 2, q = i & 3;
        int node = base + row;
        uint4 v = (node < N_NODES) ? A16[(size_t)node * 4 + q]
                                   : make_uint4(0u, 0u, 0u, 0u);
        *(uint4*)&sA[row * 40 + q * 8] = v;
    }
    __syncthreads();

    int gid = lane >> 2, tig = lane & 3;
    int m0 = wid * 16;

    float c[16][4];
#pragma unroll
    for (int nt = 0; nt < 16; nt++)
#pragma unroll
        for (int j = 0; j < 4; j++) c[nt][j] = 0.0f;

#pragma unroll
    for (int kt = 0; kt < 2; kt++) {
        int k0 = kt * 16;
        unsigned a0 = *(const unsigned*)&sA[(m0 + gid) * 40 + k0 + 2 * tig];
        unsigned a1 = *(const unsigned*)&sA[(m0 + gid + 8) * 40 + k0 + 2 * tig];
        unsigned a2 = *(const unsigned*)&sA[(m0 + gid) * 40 + k0 + 2 * tig + 8];
        unsigned a3 = *(const unsigned*)&sA[(m0 + gid + 8) * 40 + k0 + 2 * tig + 8];
        const uint2* wrow = &g_hWp1[(kt * 128) * 4 + tig];
#pragma unroll
        for (int nt = 0; nt < 16; nt++) {
            uint2 b = wrow[(nt * 8 + gid) * 4];
            asm volatile(
                "mma.sync.aligned.m16n8k16.row.col.f32.f16.f16.f32 "
                "{%0,%1,%2,%3}, {%4,%5,%6,%7}, {%8,%9}, {%0,%1,%2,%3};"
                : "+f"(c[nt][0]), "+f"(c[nt][1]), "+f"(c[nt][2]), "+f"(c[nt][3])
                : "r"(a0), "r"(a1), "r"(a2), "r"(a3),
                  "r"(b.x), "r"(b.y));
        }
    }

    int row0 = base + m0 + gid;
    int row1 = row0 + 8;
#pragma unroll
    for (int nt = 0; nt < 16; nt++) {
        int n0 = nt * 8 + 2 * tig;
        float bx = bias[n0], by = bias[n0 + 1];
        if (row0 < N_NODES)
            *(__half2*)&g_hA[(size_t)row0 * HID + n0] =
                __floats2half2_rn(fmaxf(c[nt][0] + bx, 0.f), fmaxf(c[nt][1] + by, 0.f));
        if (row1 < N_NODES)
            *(__half2*)&g_hA[(size_t)row1 * HID + n0] =
                __floats2half2_rn(fmaxf(c[nt][2] + bx, 0.f), fmaxf(c[nt][3] + by, 0.f));
    }
}

// ---- fp16 MMA GEMM, K=128: g_hagg @ g_hWp[slot] + bias, relu -> g_hA ----
__global__ __launch_bounds__(128) void gemm128_h(const float* __restrict__ bias,
                                                 int slot) {
    __shared__ __half sA[64 * 136];            // pitch 136 halves (272B)
    int tid = threadIdx.x, lane = tid & 31, wid = tid >> 5;
    int base = blockIdx.x * 64;

    const uint4* A16 = (const uint4*)g_hagg;   // 16 x 8-half chunks per node
    for (int i = tid; i < 64 * 16; i += 128) {
        int row = i >> 4, q = i & 15;
        int node = base + row;
        uint4 v = (node < N_NODES) ? A16[(size_t)node * 16 + q]
                                   : make_uint4(0u, 0u, 0u, 0u);
        *(uint4*)&sA[row * 136 + q * 8] = v;
    }
    __syncthreads();

    int gid = lane >> 2, tig = lane & 3;
    int m0 = wid * 16;
    const uint2* Wp = g_hWp[slot];

    float c[16][4];
#pragma unroll
    for (int nt = 0; nt < 16; nt++)
#pragma unroll
        for (int j = 0; j < 4; j++) c[nt][j] = 0.0f;

#pragma unroll
    for (int kt = 0; kt < 8; kt++) {
        int k0 = kt * 16;
        unsigned a0 = *(const unsigned*)&sA[(m0 + gid) * 136 + k0 + 2 * tig];
        unsigned a1 = *(const unsigned*)&sA[(m0 + gid + 8) * 136 + k0 + 2 * tig];
        unsigned a2 = *(const unsigned*)&sA[(m0 + gid) * 136 + k0 + 2 * tig + 8];
        unsigned a3 = *(const unsigned*)&sA[(m0 + gid + 8) * 136 + k0 + 2 * tig + 8];
        const uint2* wrow = &Wp[(size_t)(kt * 128) * 4 + tig];
#pragma unroll
        for (int nt = 0; nt < 16; nt++) {
            uint2 b = wrow[(nt * 8 + gid) * 4];
            asm volatile(
                "mma.sync.aligned.m16n8k16.row.col.f32.f16.f16.f32 "
                "{%0,%1,%2,%3}, {%4,%5,%6,%7}, {%8,%9}, {%0,%1,%2,%3};"
                : "+f"(c[nt][0]), "+f"(c[nt][1]), "+f"(c[nt][2]), "+f"(c[nt][3])
                : "r"(a0), "r"(a1), "r"(a2), "r"(a3),
                  "r"(b.x), "r"(b.y));
        }
    }

    int row0 = base + m0 + gid;
    int row1 = row0 + 8;
#pragma unroll
    for (int nt = 0; nt < 16; nt++) {
        int n0 = nt * 8 + 2 * tig;
        float bx = bias[n0], by = bias[n0 + 1];
        if (row0 < N_NODES)
            *(__half2*)&g_hA[(size_t)row0 * HID + n0] =
                __floats2half2_rn(fmaxf(c[nt][0] + bx, 0.f), fmaxf(c[nt][1] + by, 0.f));
        if (row1 < N_NODES)
            *(__half2*)&g_hA[(size_t)row1 * HID + n0] =
                __floats2half2_rn(fmaxf(c[nt][2] + bx, 0.f), fmaxf(c[nt][3] + by, 0.f));
    }
}

// ---- fused mean-pool + head: block per graph ----
__global__ __launch_bounds__(128) void poolhead_k(const float* __restrict__ Wout,
                                                  const float* __restrict__ bout,
                                                  float* __restrict__ out) {
    __shared__ float sp[HID];
    int g = blockIdx.x;
    int c = threadIdx.x;
    int s = g_gstart[g], e = g_gstart[g + 1];
    float acc = 0.0f;
    for (int n = s; n < e; n++) acc += __half2float(g_hA[(size_t)n * HID + c]);
    sp[c] = acc / fmaxf((float)(e - s), 1.0f);
    __syncthreads();
    if (c < OUT_F) {
        float o = bout[c];
#pragma unroll 8
        for (int k = 0; k < HID; k++)
            o = fmaf(sp[k], Wout[k * OUT_F + c], o);
        out[g * OUT_F + c] = o;
    }
}

// ---------------- launch (kernel launches ONLY — graph-capture safe) ----------------
extern "C" void kernel_launch(void* const* d_in, const int* in_sizes, int n_in,
                              void* d_out, int out_size) {
    const float* x     = (const float*)d_in[0];
    const int*   ei    = (const int*)d_in[1];    // int32 (JAX x64 disabled)
    const int*   batch = (const int*)d_in[2];    // int32
    const float* W1 = (const float*)d_in[3];
    const float* b1 = (const float*)d_in[4];
    const float* W2 = (const float*)d_in[5];
    const float* b2 = (const float*)d_in[6];
    const float* W3 = (const float*)d_in[7];
    const float* b3 = (const float*)d_in[8];
    const float* Wout = (const float*)d_in[9];
    const float* bout = (const float*)d_in[10];
    float* out = (float*)d_out;

    const int NB = 256;
    int nblk_edges = (N_EDGES + NB - 1) / NB;
    int nblk_warpnode = (N_NODES * 32 + NB - 1) / NB;
    int nblk_halfwarp = ((N_NODES + 1) / 2 * 32 + NB - 1) / NB;   // 2 nodes/warp
    int nblk_tc = (N_NODES + 63) / 64;

    // CSR build + weight packing (g_cnt/g_fill zeroed by previous scan1_k / init)
    hist_k<<<nblk_edges, NB>>>(ei);
    packAll_k<<<36, 256>>>(W1, W2, W3);
    scan1_k<<<NBLK_SCAN, 1024>>>();          // scan + dinv + re-zero cnt/fill
    scan23_k<<<NBLK_SCAN, 1024>>>(batch);    // offsets + total + graph bounds
    fill_k<<<nblk_edges, NB>>>(ei);

    // layer 1: agg x -> fp16 [N,32], tensor GEMM -> g_hA
    agg20_k<<<nblk_warpnode, NB>>>(x);
    gemm32_h<<<nblk_tc, 128>>>(b1);

    // layer 2: g_hA -> g_hagg -> g_hA
    agg128h_k<<<nblk_halfwarp, NB>>>();
    gemm128_h<<<nblk_tc, 128>>>(b2, 0);

    // layer 3: g_hA -> g_hagg -> g_hA
    agg128h_k<<<nblk_halfwarp, NB>>>();
    gemm128_h<<<nblk_tc, 128>>>(b3, 1);

    // pool + head
    poolhead_k<<<N_GRAPHS, 128>>>(Wout, bout, out);
}

// round 16
// speedup vs baseline: 1.0070x; 1.0070x over previous
#include <cuda_runtime.h>
#include <cuda_fp16.h>
#include <math.h>

#define N_NODES  100000
#define N_EDGES  1600000
#define N_GRAPHS 512
#define F_IN     20
#define HID      128
#define OUT_F    64
#define NBLK_SCAN ((N_NODES + 1023) / 1024)   // 98
#define NBLK_PACK 9                            // 9*1024 >= 9216 pack items
#define SCAN_FLAG 0x80000000u

// ---------------- static device scratch (no runtime allocation) ----------------
__device__ int      g_cnt[N_NODES];     // zero-init; re-zeroed by scanAll_k each run
__device__ int      g_fill[N_NODES];    // zero-init; re-zeroed by scanAll_k each run
__device__ int      g_rowptr[N_NODES + 1];
__device__ float    g_dinv[N_NODES];
__device__ int2     g_cw[N_EDGES];            // {src, w as float bits}
__device__ __align__(16) __half g_hx32[(size_t)N_NODES * 32];   // layer-1 agg, fp16 K=32 padded
__device__ __align__(16) __half g_hA[(size_t)N_NODES * HID];    // fp16 activations
__device__ __align__(16) __half g_hagg[(size_t)N_NODES * HID];  // fp16 aggregate (GEMM A)
__device__ uint2    g_hWp[2][8 * 128 * 4];    // W2/W3 fp16 B-frag layout (32KB each)
__device__ uint2    g_hWp1[2 * 128 * 4];      // W1 fp16 B-frag layout (K=32 padded)
__device__ int      g_gstart[N_GRAPHS + 1];
__device__ unsigned g_state[NBLK_SCAN];       // decoupled-lookback state; zeroed by hist_k

// ---------------- CSR build ----------------
__global__ void hist_k(const int* __restrict__ ei) {
    if (blockIdx.x == 0 && threadIdx.x < NBLK_SCAN)
        g_state[threadIdx.x] = 0u;            // reset lookback state for this replay
    int e = blockIdx.x * blockDim.x + threadIdx.x;
    if (e < N_EDGES) {
        int d = ei[N_EDGES + e];
        atomicAdd(&g_cnt[d], 1);
    }
}

// single-kernel scan (decoupled lookback) + dinv + cnt/fill re-zero
// + graph bounds + weight packing (extra blocks). Single wave: 107 blocks < 148 SMs.
__global__ __launch_bounds__(1024) void scanAll_k(const int* __restrict__ batch,
                                                  const float* __restrict__ W1,
                                                  const float* __restrict__ W2,
                                                  const float* __restrict__ W3) {
    int b = blockIdx.x;
    int tid = threadIdx.x, lane = tid & 31, wid = tid >> 5;

    if (b >= NBLK_SCAN) {
        // ---- pack blocks ----
        int idx = (b - NBLK_SCAN) * 1024 + tid;
        if (idx < 8192) {
            const float* W = (idx < 4096) ? W2 : W3;
            int slot = idx >> 12;
            int l = idx & 4095;
            int tig = l & 3;
            int n   = (l >> 2) & 127;
            int kt  = l >> 9;
            int k0  = kt * 16 + 2 * tig;
            __half2 lo = __floats2half2_rn(W[(k0 + 0) * HID + n], W[(k0 + 1) * HID + n]);
            __half2 hi = __floats2half2_rn(W[(k0 + 8) * HID + n], W[(k0 + 9) * HID + n]);
            uint2 u;
            u.x = *(unsigned*)&lo;
            u.y = *(unsigned*)&hi;
            g_hWp[slot][l] = u;
        } else if (idx < 8192 + 1024) {
            int l = idx - 8192;
            int tig = l & 3;
            int n   = (l >> 2) & 127;
            int kt  = l >> 9;
            int k0  = kt * 16 + 2 * tig;
            float w0 = (k0 + 0 < F_IN) ? W1[(k0 + 0) * HID + n] : 0.f;
            float w1 = (k0 + 1 < F_IN) ? W1[(k0 + 1) * HID + n] : 0.f;
            float w2 = (k0 + 8 < F_IN) ? W1[(k0 + 8) * HID + n] : 0.f;
            float w3 = (k0 + 9 < F_IN) ? W1[(k0 + 9) * HID + n] : 0.f;
            __half2 lo = __floats2half2_rn(w0, w1);
            __half2 hi = __floats2half2_rn(w2, w3);
            uint2 u;
            u.x = *(unsigned*)&lo;
            u.y = *(unsigned*)&hi;
            g_hWp1[l] = u;
        }
        return;
    }

    // ---- scan blocks ----
    __shared__ int wsum[32];
    __shared__ int s_off;
    int i = b * 1024 + tid;
    int v = 0;
    if (i < N_NODES) {
        v = g_cnt[i];
        g_cnt[i] = 0;                    // ready for next replay
        g_fill[i] = 0;                   // ready for fill_k
        g_dinv[i] = rsqrtf((float)(v + 1));   // +1 self loop
        // graph segment bounds from sorted batch
        int bb = batch[i];
        if (i == 0) {
            for (int g = 0; g <= bb; g++) g_gstart[g] = 0;
        }
        int bn = (i + 1 < N_NODES) ? batch[i + 1] : N_GRAPHS;
        for (int g = bb + 1; g <= bn; g++) g_gstart[g] = i + 1;
    }
    int xv = v;
#pragma unroll
    for (int d = 1; d < 32; d <<= 1) {
        int t = __shfl_up_sync(0xffffffffu, xv, d);
        if (lane >= d) xv += t;
    }
    if (lane == 31) wsum[wid] = xv;
    __syncthreads();
    if (wid == 0) {
        int y = wsum[lane];
#pragma unroll
        for (int d = 1; d < 32; d <<= 1) {
            int t = __shfl_up_sync(0xffffffffu, y, d);
            if (lane >= d) y += t;
        }
        wsum[lane] = y;
    }
    __syncthreads();
    int incl = xv + (wid > 0 ? wsum[wid - 1] : 0);
    int btotal = wsum[31];

    // publish this block's aggregate (flag in high bit; totals < 2^31)
    if (tid == 0)
        atomicExch(&g_state[b], (unsigned)btotal | SCAN_FLAG);

    // warp 0: spin-gather aggregates of preceding blocks
    if (wid == 0) {
        unsigned acc = 0;
        for (int j = lane; j < b; j += 32) {
            volatile unsigned* sp = (volatile unsigned*)&g_state[j];
            unsigned s;
            do { s = *sp; } while (!(s & SCAN_FLAG));
            acc += s & ~SCAN_FLAG;
        }
#pragma unroll
        for (int d = 16; d > 0; d >>= 1)
            acc += __shfl_down_sync(0xffffffffu, acc, d);
        if (lane == 0) s_off = (int)acc;
    }
    __syncthreads();
    int offset = s_off;
    if (i < N_NODES) g_rowptr[i] = offset + incl - v;
    if (b == NBLK_SCAN - 1 && tid == 1023) g_rowptr[N_NODES] = offset + btotal;
}

__global__ void fill_k(const int* __restrict__ ei) {
    int e = blockIdx.x * blockDim.x + threadIdx.x;
    if (e < N_EDGES) {
        int s = ei[e];
        int d = ei[N_EDGES + e];
        int p = g_rowptr[d] + atomicAdd(&g_fill[d], 1);
        int2 cw;
        cw.x = s;
        cw.y = __float_as_int(g_dinv[s]);
        g_cw[p] = cw;
    }
}

// ---------------- layer-1 aggregation: x fp32 -> g_hx32 fp16 [N,32] ----------------
// warp per node; edge loop unrolled x4; gathers via .cg (L2-only)
__global__ __launch_bounds__(256) void agg20_k(const float* __restrict__ x) {
    int warp = (blockIdx.x * blockDim.x + threadIdx.x) >> 5;
    int lane = threadIdx.x & 31;
    if (warp >= N_NODES) return;
    int beg = g_rowptr[warp], end = g_rowptr[warp + 1];
    float di = g_dinv[warp];
    float acc = 0.0f;
    if (lane < F_IN) acc = di * __ldcg(&x[(size_t)warp * F_IN + lane]);
    int e = beg;
    for (; e + 3 < end; e += 4) {
        int2 c0 = g_cw[e], c1 = g_cw[e + 1], c2 = g_cw[e + 2], c3 = g_cw[e + 3];
        float v0 = 0.f, v1 = 0.f, v2 = 0.f, v3 = 0.f;
        if (lane < F_IN) {
            v0 = __ldcg(&x[(size_t)c0.x * F_IN + lane]);
            v1 = __ldcg(&x[(size_t)c1.x * F_IN + lane]);
            v2 = __ldcg(&x[(size_t)c2.x * F_IN + lane]);
            v3 = __ldcg(&x[(size_t)c3.x * F_IN + lane]);
        }
        acc = fmaf(__int_as_float(c0.y), v0, acc);
        acc = fmaf(__int_as_float(c1.y), v1, acc);
        acc = fmaf(__int_as_float(c2.y), v2, acc);
        acc = fmaf(__int_as_float(c3.y), v3, acc);
    }
    for (; e < end; e++) {
        int2 cw = g_cw[e];
        if (lane < F_IN)
            acc = fmaf(__int_as_float(cw.y), __ldcg(&x[(size_t)cw.x * F_IN + lane]), acc);
    }
    g_hx32[(size_t)warp * 32 + lane] = __float2half_rn(lane < F_IN ? di * acc : 0.0f);
}

// ---------------- fp16-gather aggregation: g_hA -> g_hagg ----------------
// TWO nodes per warp: half-warp (16 lanes) per node, uint4 (16B, 8ch) per lane.
// gathers via .cg (L2-only, no L1 allocation)
#define ACC8(U, W) { \
    float2 f0 = __half22float2(*(const __half2*)&(U).x); \
    float2 f1 = __half22float2(*(const __half2*)&(U).y); \
    float2 f2 = __half22float2(*(const __half2*)&(U).z); \
    float2 f3 = __half22float2(*(const __half2*)&(U).w); \
    acc[0] = fmaf((W), f0.x, acc[0]); acc[1] = fmaf((W), f0.y, acc[1]); \
    acc[2] = fmaf((W), f1.x, acc[2]); acc[3] = fmaf((W), f1.y, acc[3]); \
    acc[4] = fmaf((W), f2.x, acc[4]); acc[5] = fmaf((W), f2.y, acc[5]); \
    acc[6] = fmaf((W), f3.x, acc[6]); acc[7] = fmaf((W), f3.y, acc[7]); }

__global__ __launch_bounds__(256) void agg128h_k() {
    int warp = (blockIdx.x * blockDim.x + threadIdx.x) >> 5;
    int lane = threadIdx.x & 31;
    int half = lane >> 4, hl = lane & 15;
    int node = warp * 2 + half;
    if (node >= N_NODES) return;
    const uint4* H16 = (const uint4*)g_hA;   // 16 x 16B per node row
    int beg = g_rowptr[node], end = g_rowptr[node + 1];
    float di = g_dinv[node];

    float acc[8];
    {   // self loop
        uint4 u = __ldcg(&H16[(size_t)node * 16 + hl]);
        float2 f0 = __half22float2(*(const __half2*)&u.x);
        float2 f1 = __half22float2(*(const __half2*)&u.y);
        float2 f2 = __half22float2(*(const __half2*)&u.z);
        float2 f3 = __half22float2(*(const __half2*)&u.w);
        acc[0] = di * f0.x; acc[1] = di * f0.y;
        acc[2] = di * f1.x; acc[3] = di * f1.y;
        acc[4] = di * f2.x; acc[5] = di * f2.y;
        acc[6] = di * f3.x; acc[7] = di * f3.y;
    }

    int e = beg;
    for (; e + 3 < end; e += 4) {
        int2 c0 = g_cw[e], c1 = g_cw[e + 1], c2 = g_cw[e + 2], c3 = g_cw[e + 3];
        uint4 u0 = __ldcg(&H16[(size_t)c0.x * 16 + hl]);
        uint4 u1 = __ldcg(&H16[(size_t)c1.x * 16 + hl]);
        uint4 u2 = __ldcg(&H16[(size_t)c2.x * 16 + hl]);
        uint4 u3 = __ldcg(&H16[(size_t)c3.x * 16 + hl]);
        ACC8(u0, __int_as_float(c0.y))
        ACC8(u1, __int_as_float(c1.y))
        ACC8(u2, __int_as_float(c2.y))
        ACC8(u3, __int_as_float(c3.y))
    }
    for (; e < end; e++) {
        int2 cw = g_cw[e];
        uint4 u = __ldcg(&H16[(size_t)cw.x * 16 + hl]);
        ACC8(u, __int_as_float(cw.y))
    }

    uint4 o;
    __half2 h0 = __floats2half2_rn(di * acc[0], di * acc[1]);
    __half2 h1 = __floats2half2_rn(di * acc[2], di * acc[3]);
    __half2 h2 = __floats2half2_rn(di * acc[4], di * acc[5]);
    __half2 h3 = __floats2half2_rn(di * acc[6], di * acc[7]);
    o.x = *(unsigned*)&h0; o.y = *(unsigned*)&h1;
    o.z = *(unsigned*)&h2; o.w = *(unsigned*)&h3;
    ((uint4*)g_hagg)[(size_t)node * 16 + hl] = o;
}

// ---- fp16 MMA GEMM, K=32: g_hx32[N,32] @ g_hWp1 + bias, relu -> g_hA ----
__global__ __launch_bounds__(128) void gemm32_h(const float* __restrict__ bias) {
    __shared__ __half sA[64 * 40];             // pitch 40 halves (80B)
    int tid = threadIdx.x, lane = tid & 31, wid = tid >> 5;
    int base = blockIdx.x * 64;

    const uint4* A16 = (const uint4*)g_hx32;   // 4 x 8-half chunks per node
    for (int i = tid; i < 64 * 4; i += 128) {
        int row = i >> 2, q = i & 3;
        int node = base + row;
        uint4 v = (node < N_NODES) ? A16[(size_t)node * 4 + q]
                                   : make_uint4(0u, 0u, 0u, 0u);
        *(uint4*)&sA[row * 40 + q * 8] = v;
    }
    __syncthreads();

    int gid = lane >> 2, tig = lane & 3;
    int m0 = wid * 16;

    float c[16][4];
#pragma unroll
    for (int nt = 0; nt < 16; nt++)
#pragma unroll
        for (int j = 0; j < 4; j++) c[nt][j] = 0.0f;

#pragma unroll
    for (int kt = 0; kt < 2; kt++) {
        int k0 = kt * 16;
        unsigned a0 = *(const unsigned*)&sA[(m0 + gid) * 40 + k0 + 2 * tig];
        unsigned a1 = *(const unsigned*)&sA[(m0 + gid + 8) * 40 + k0 + 2 * tig];
        unsigned a2 = *(const unsigned*)&sA[(m0 + gid) * 40 + k0 + 2 * tig + 8];
        unsigned a3 = *(const unsigned*)&sA[(m0 + gid + 8) * 40 + k0 + 2 * tig + 8];
        const uint2* wrow = &g_hWp1[(kt * 128) * 4 + tig];
#pragma unroll
        for (int nt = 0; nt < 16; nt++) {
            uint2 b = wrow[(nt * 8 + gid) * 4];
            asm volatile(
                "mma.sync.aligned.m16n8k16.row.col.f32.f16.f16.f32 "
                "{%0,%1,%2,%3}, {%4,%5,%6,%7}, {%8,%9}, {%0,%1,%2,%3};"
                : "+f"(c[nt][0]), "+f"(c[nt][1]), "+f"(c[nt][2]), "+f"(c[nt][3])
                : "r"(a0), "r"(a1), "r"(a2), "r"(a3),
                  "r"(b.x), "r"(b.y));
        }
    }

    int row0 = base + m0 + gid;
    int row1 = row0 + 8;
#pragma unroll
    for (int nt = 0; nt < 16; nt++) {
        int n0 = nt * 8 + 2 * tig;
        float bx = bias[n0], by = bias[n0 + 1];
        if (row0 < N_NODES)
            *(__half2*)&g_hA[(size_t)row0 * HID + n0] =
                __floats2half2_rn(fmaxf(c[nt][0] + bx, 0.f), fmaxf(c[nt][1] + by, 0.f));
        if (row1 < N_NODES)
            *(__half2*)&g_hA[(size_t)row1 * HID + n0] =
                __floats2half2_rn(fmaxf(c[nt][2] + bx, 0.f), fmaxf(c[nt][3] + by, 0.f));
    }
}

// ---- fp16 MMA GEMM, K=128: g_hagg @ g_hWp[slot] + bias, relu -> g_hA ----
__global__ __launch_bounds__(128) void gemm128_h(const float* __restrict__ bias,
                                                 int slot) {
    __shared__ __half sA[64 * 136];            // pitch 136 halves (272B)
    int tid = threadIdx.x, lane = tid & 31, wid = tid >> 5;
    int base = blockIdx.x * 64;

    const uint4* A16 = (const uint4*)g_hagg;   // 16 x 8-half chunks per node
    for (int i = tid; i < 64 * 16; i += 128) {
        int row = i >> 4, q = i & 15;
        int node = base + row;
        uint4 v = (node < N_NODES) ? A16[(size_t)node * 16 + q]
                                   : make_uint4(0u, 0u, 0u, 0u);
        *(uint4*)&sA[row * 136 + q * 8] = v;
    }
    __syncthreads();

    int gid = lane >> 2, tig = lane & 3;
    int m0 = wid * 16;
    const uint2* Wp = g_hWp[slot];

    float c[16][4];
#pragma unroll
    for (int nt = 0; nt < 16; nt++)
#pragma unroll
        for (int j = 0; j < 4; j++) c[nt][j] = 0.0f;

#pragma unroll
    for (int kt = 0; kt < 8; kt++) {
        int k0 = kt * 16;
        unsigned a0 = *(const unsigned*)&sA[(m0 + gid) * 136 + k0 + 2 * tig];
        unsigned a1 = *(const unsigned*)&sA[(m0 + gid + 8) * 136 + k0 + 2 * tig];
        unsigned a2 = *(const unsigned*)&sA[(m0 + gid) * 136 + k0 + 2 * tig + 8];
        unsigned a3 = *(const unsigned*)&sA[(m0 + gid + 8) * 136 + k0 + 2 * tig + 8];
        const uint2* wrow = &Wp[(size_t)(kt * 128) * 4 + tig];
#pragma unroll
        for (int nt = 0; nt < 16; nt++) {
            uint2 b = wrow[(nt * 8 + gid) * 4];
            asm volatile(
                "mma.sync.aligned.m16n8k16.row.col.f32.f16.f16.f32 "
                "{%0,%1,%2,%3}, {%4,%5,%6,%7}, {%8,%9}, {%0,%1,%2,%3};"
                : "+f"(c[nt][0]), "+f"(c[nt][1]), "+f"(c[nt][2]), "+f"(c[nt][3])
                : "r"(a0), "r"(a1), "r"(a2), "r"(a3),
                  "r"(b.x), "r"(b.y));
        }
    }

    int row0 = base + m0 + gid;
    int row1 = row0 + 8;
#pragma unroll
    for (int nt = 0; nt < 16; nt++) {
        int n0 = nt * 8 + 2 * tig;
        float bx = bias[n0], by = bias[n0 + 1];
        if (row0 < N_NODES)
            *(__half2*)&g_hA[(size_t)row0 * HID + n0] =
                __floats2half2_rn(fmaxf(c[nt][0] + bx, 0.f), fmaxf(c[nt][1] + by, 0.f));
        if (row1 < N_NODES)
            *(__half2*)&g_hA[(size_t)row1 * HID + n0] =
                __floats2half2_rn(fmaxf(c[nt][2] + bx, 0.f), fmaxf(c[nt][3] + by, 0.f));
    }
}

// ---- fused mean-pool + head: block per graph ----
__global__ __launch_bounds__(128) void poolhead_k(const float* __restrict__ Wout,
                                                  const float* __restrict__ bout,
                                                  float* __restrict__ out) {
    __shared__ float sp[HID];
    int g = blockIdx.x;
    int c = threadIdx.x;
    int s = g_gstart[g], e = g_gstart[g + 1];
    float acc = 0.0f;
    for (int n = s; n < e; n++) acc += __half2float(g_hA[(size_t)n * HID + c]);
    sp[c] = acc / fmaxf((float)(e - s), 1.0f);
    __syncthreads();
    if (c < OUT_F) {
        float o = bout[c];
#pragma unroll 8
        for (int k = 0; k < HID; k++)
            o = fmaf(sp[k], Wout[k * OUT_F + c], o);
        out[g * OUT_F + c] = o;
    }
}

// ---------------- launch (kernel launches ONLY — graph-capture safe) ----------------
extern "C" void kernel_launch(void* const* d_in, const int* in_sizes, int n_in,
                              void* d_out, int out_size) {
    const float* x     = (const float*)d_in[0];
    const int*   ei    = (const int*)d_in[1];    // int32 (JAX x64 disabled)
    const int*   batch = (const int*)d_in[2];    // int32
    const float* W1 = (const float*)d_in[3];
    const float* b1 = (const float*)d_in[4];
    const float* W2 = (const float*)d_in[5];
    const float* b2 = (const float*)d_in[6];
    const float* W3 = (const float*)d_in[7];
    const float* b3 = (const float*)d_in[8];
    const float* Wout = (const float*)d_in[9];
    const float* bout = (const float*)d_in[10];
    float* out = (float*)d_out;

    const int NB = 256;
    int nblk_edges = (N_EDGES + NB - 1) / NB;
    int nblk_warpnode = (N_NODES * 32 + NB - 1) / NB;
    int nblk_halfwarp = ((N_NODES + 1) / 2 * 32 + NB - 1) / NB;   // 2 nodes/warp
    int nblk_tc = (N_NODES + 63) / 64;

    // 1. histogram (+ lookback-state reset)
    hist_k<<<nblk_edges, NB>>>(ei);
    // 2. scan + dinv + bounds + weight packing (single wave, lookback)
    scanAll_k<<<NBLK_SCAN + NBLK_PACK, 1024>>>(batch, W1, W2, W3);
    // 3. CSR fill
    fill_k<<<nblk_edges, NB>>>(ei);
    // 4-5. layer 1
    agg20_k<<<nblk_warpnode, NB>>>(x);
    gemm32_h<<<nblk_tc, 128>>>(b1);
    // 6-7. layer 2   (launch #6 = agg128h_k -> ncu profile target)
    agg128h_k<<<nblk_halfwarp, NB>>>();
    gemm128_h<<<nblk_tc, 128>>>(b2, 0);
    // 8-9. layer 3
    agg128h_k<<<nblk_halfwarp, NB>>>();
    gemm128_h<<<nblk_tc, 128>>>(b3, 1);
    // 10. pool + head
    poolhead_k<<<N_GRAPHS, 128>>>(Wout, bout, out);
}

// round 17
// speedup vs baseline: 1.0357x; 1.0286x over previous
#include <cuda_runtime.h>
#include <cuda_fp16.h>
#include <math.h>

#define N_NODES  100000
#define N_EDGES  1600000
#define N_GRAPHS 512
#define F_IN     20
#define HID      128
#define OUT_F    64
#define NBLK_SCAN ((N_NODES + 1023) / 1024)   // 98
#define NBLK_PACK 9                            // 9*1024 >= 9216 pack items
#define SCAN_FLAG 0x80000000u

// ---------------- static device scratch (no runtime allocation) ----------------
__device__ int      g_cnt[N_NODES];     // zero-init; re-zeroed by scanAll_k each run
__device__ int      g_fill[N_NODES];    // zero-init; re-zeroed by scanAll_k each run
__device__ int      g_rowptr[N_NODES + 1];
__device__ float    g_dinv[N_NODES];
__device__ int2     g_cw[N_EDGES];            // {src, w as float bits}
__device__ __align__(16) __half g_hx32[(size_t)N_NODES * 32];   // layer-1 agg out, fp16 K=32
__device__ __align__(16) __half g_hA[(size_t)N_NODES * HID];    // fp16 activations
__device__ __align__(16) __half g_hagg[(size_t)N_NODES * HID];  // fp16 aggregate (GEMM A);
                                                                // first 64B/node reused as x16
__device__ uint2    g_hWp[2][8 * 128 * 4];    // W2/W3 fp16 B-frag layout (32KB each)
__device__ uint2    g_hWp1[2 * 128 * 4];      // W1 fp16 B-frag layout (K=32 padded)
__device__ int      g_gstart[N_GRAPHS + 1];
__device__ unsigned g_state[NBLK_SCAN];       // decoupled-lookback state; zeroed by hist_k

// ---------------- CSR build (+ x -> fp16 [N,32] conversion) ----------------
__global__ void hist_k(const int* __restrict__ ei, const float* __restrict__ x) {
    int t = blockIdx.x * blockDim.x + threadIdx.x;
    if (blockIdx.x == 0 && threadIdx.x < NBLK_SCAN)
        g_state[threadIdx.x] = 0u;            // reset lookback state for this replay
    if (t < N_EDGES) {
        int d = ei[N_EDGES + t];
        atomicAdd(&g_cnt[d], 1);
    }
    // convert x to fp16 padded [N,32], stored in g_hagg (free until layer 2)
    if (t < N_NODES * 8) {
        int node = t >> 3, q = t & 3, hi4 = (t >> 2) & 1;   // chunk = (hi4*4+q)? no:
        // simpler: chunk index q8 = t & 7 -> channels 4*q8 .. 4*q8+3
        int q8 = t & 7;
        int ch = q8 * 4;
        const float* xr = &x[(size_t)node * F_IN];
        float v0 = (ch + 0 < F_IN) ? xr[ch + 0] : 0.f;
        float v1 = (ch + 1 < F_IN) ? xr[ch + 1] : 0.f;
        float v2 = (ch + 2 < F_IN) ? xr[ch + 2] : 0.f;
        float v3 = (ch + 3 < F_IN) ? xr[ch + 3] : 0.f;
        __half2 lo = __floats2half2_rn(v0, v1);
        __half2 hi = __floats2half2_rn(v2, v3);
        uint2 u;
        u.x = *(unsigned*)&lo;
        u.y = *(unsigned*)&hi;
        ((uint2*)g_hagg)[t] = u;
        (void)q; (void)hi4;
    }
}

// single-kernel scan (decoupled lookback) + dinv + cnt/fill re-zero
// + graph bounds + weight packing (extra blocks).
__global__ __launch_bounds__(1024) void scanAll_k(const int* __restrict__ batch,
                                                  const float* __restrict__ W1,
                                                  const float* __restrict__ W2,
                                                  const float* __restrict__ W3) {
    int b = blockIdx.x;
    int tid = threadIdx.x, lane = tid & 31, wid = tid >> 5;

    if (b >= NBLK_SCAN) {
        // ---- pack blocks ----
        int idx = (b - NBLK_SCAN) * 1024 + tid;
        if (idx < 8192) {
            const float* W = (idx < 4096) ? W2 : W3;
            int slot = idx >> 12;
            int l = idx & 4095;
            int tig = l & 3;
            int n   = (l >> 2) & 127;
            int kt  = l >> 9;
            int k0  = kt * 16 + 2 * tig;
            __half2 lo = __floats2half2_rn(W[(k0 + 0) * HID + n], W[(k0 + 1) * HID + n]);
            __half2 hi = __floats2half2_rn(W[(k0 + 8) * HID + n], W[(k0 + 9) * HID + n]);
            uint2 u;
            u.x = *(unsigned*)&lo;
            u.y = *(unsigned*)&hi;
            g_hWp[slot][l] = u;
        } else if (idx < 8192 + 1024) {
            int l = idx - 8192;
            int tig = l & 3;
            int n   = (l >> 2) & 127;
            int kt  = l >> 9;
            int k0  = kt * 16 + 2 * tig;
            float w0 = (k0 + 0 < F_IN) ? W1[(k0 + 0) * HID + n] : 0.f;
            float w1 = (k0 + 1 < F_IN) ? W1[(k0 + 1) * HID + n] : 0.f;
            float w2 = (k0 + 8 < F_IN) ? W1[(k0 + 8) * HID + n] : 0.f;
            float w3 = (k0 + 9 < F_IN) ? W1[(k0 + 9) * HID + n] : 0.f;
            __half2 lo = __floats2half2_rn(w0, w1);
            __half2 hi = __floats2half2_rn(w2, w3);
            uint2 u;
            u.x = *(unsigned*)&lo;
            u.y = *(unsigned*)&hi;
            g_hWp1[l] = u;
        }
        return;
    }

    // ---- scan blocks ----
    __shared__ int wsum[32];
    __shared__ int s_off;
    int i = b * 1024 + tid;
    int v = 0;
    if (i < N_NODES) {
        v = g_cnt[i];
        g_cnt[i] = 0;                    // ready for next replay
        g_fill[i] = 0;                   // ready for fill_k
        g_dinv[i] = rsqrtf((float)(v + 1));   // +1 self loop
        // graph segment bounds from sorted batch
        int bb = batch[i];
        if (i == 0) {
            for (int g = 0; g <= bb; g++) g_gstart[g] = 0;
        }
        int bn = (i + 1 < N_NODES) ? batch[i + 1] : N_GRAPHS;
        for (int g = bb + 1; g <= bn; g++) g_gstart[g] = i + 1;
    }
    int xv = v;
#pragma unroll
    for (int d = 1; d < 32; d <<= 1) {
        int t = __shfl_up_sync(0xffffffffu, xv, d);
        if (lane >= d) xv += t;
    }
    if (lane == 31) wsum[wid] = xv;
    __syncthreads();
    if (wid == 0) {
        int y = wsum[lane];
#pragma unroll
        for (int d = 1; d < 32; d <<= 1) {
            int t = __shfl_up_sync(0xffffffffu, y, d);
            if (lane >= d) y += t;
        }
        wsum[lane] = y;
    }
    __syncthreads();
    int incl = xv + (wid > 0 ? wsum[wid - 1] : 0);
    int btotal = wsum[31];

    if (tid == 0)
        atomicExch(&g_state[b], (unsigned)btotal | SCAN_FLAG);

    if (wid == 0) {
        unsigned acc = 0;
        for (int j = lane; j < b; j += 32) {
            volatile unsigned* sp = (volatile unsigned*)&g_state[j];
            unsigned s;
            do { s = *sp; } while (!(s & SCAN_FLAG));
            acc += s & ~SCAN_FLAG;
        }
#pragma unroll
        for (int d = 16; d > 0; d >>= 1)
            acc += __shfl_down_sync(0xffffffffu, acc, d);
        if (lane == 0) s_off = (int)acc;
    }
    __syncthreads();
    int offset = s_off;
    if (i < N_NODES) g_rowptr[i] = offset + incl - v;
    if (b == NBLK_SCAN - 1 && tid == 1023) g_rowptr[N_NODES] = offset + btotal;
}

__global__ void fill_k(const int* __restrict__ ei) {
    int e = blockIdx.x * blockDim.x + threadIdx.x;
    if (e < N_EDGES) {
        int s = ei[e];
        int d = ei[N_EDGES + e];
        int p = g_rowptr[d] + atomicAdd(&g_fill[d], 1);
        int2 cw;
        cw.x = s;
        cw.y = __float_as_int(g_dinv[s]);
        g_cw[p] = cw;
    }
}

// ---------------- layer-1 aggregation: x16 (g_hagg) -> g_hx32 fp16 [N,32] ----------------
// FOUR nodes per warp: 8 lanes per node, uint2 (4ch) per lane.
__global__ __launch_bounds__(256) void agg20q_k() {
    int warp = (blockIdx.x * blockDim.x + threadIdx.x) >> 5;
    int lane = threadIdx.x & 31;
    int quarter = lane >> 3, hl = lane & 7;
    int node = warp * 4 + quarter;
    if (node >= N_NODES) return;
    const uint2* X8 = (const uint2*)g_hagg;   // 8 x 8B per node row (fp16 padded)
    int beg = g_rowptr[node], end = g_rowptr[node + 1];
    float di = g_dinv[node];

    float a0, a1, a2, a3;
    {   // self loop
        uint2 u = __ldcg(&X8[(size_t)node * 8 + hl]);
        float2 f0 = __half22float2(*(const __half2*)&u.x);
        float2 f1 = __half22float2(*(const __half2*)&u.y);
        a0 = di * f0.x; a1 = di * f0.y; a2 = di * f1.x; a3 = di * f1.y;
    }

    int e = beg;
    for (; e + 1 < end; e += 2) {
        int2 c0 = g_cw[e], c1 = g_cw[e + 1];
        uint2 u0 = __ldcg(&X8[(size_t)c0.x * 8 + hl]);
        uint2 u1 = __ldcg(&X8[(size_t)c1.x * 8 + hl]);
        float w0 = __int_as_float(c0.y), w1 = __int_as_float(c1.y);
        float2 f0 = __half22float2(*(const __half2*)&u0.x);
        float2 f1 = __half22float2(*(const __half2*)&u0.y);
        a0 = fmaf(w0, f0.x, a0); a1 = fmaf(w0, f0.y, a1);
        a2 = fmaf(w0, f1.x, a2); a3 = fmaf(w0, f1.y, a3);
        f0 = __half22float2(*(const __half2*)&u1.x);
        f1 = __half22float2(*(const __half2*)&u1.y);
        a0 = fmaf(w1, f0.x, a0); a1 = fmaf(w1, f0.y, a1);
        a2 = fmaf(w1, f1.x, a2); a3 = fmaf(w1, f1.y, a3);
    }
    if (e < end) {
        int2 cw = g_cw[e];
        float w = __int_as_float(cw.y);
        uint2 u = __ldcg(&X8[(size_t)cw.x * 8 + hl]);
        float2 f0 = __half22float2(*(const __half2*)&u.x);
        float2 f1 = __half22float2(*(const __half2*)&u.y);
        a0 = fmaf(w, f0.x, a0); a1 = fmaf(w, f0.y, a1);
        a2 = fmaf(w, f1.x, a2); a3 = fmaf(w, f1.y, a3);
    }

    __half2 lo = __floats2half2_rn(di * a0, di * a1);
    __half2 hi = __floats2half2_rn(di * a2, di * a3);
    uint2 o;
    o.x = *(unsigned*)&lo;
    o.y = *(unsigned*)&hi;
    ((uint2*)g_hx32)[(size_t)node * 8 + hl] = o;
}

// ---------------- fp16-gather aggregation: g_hA -> g_hagg ----------------
// TWO nodes per warp: half-warp (16 lanes) per node, uint4 (16B, 8ch) per lane.
#define ACC8(U, W) { \
    float2 f0 = __half22float2(*(const __half2*)&(U).x); \
    float2 f1 = __half22float2(*(const __half2*)&(U).y); \
    float2 f2 = __half22float2(*(const __half2*)&(U).z); \
    float2 f3 = __half22float2(*(const __half2*)&(U).w); \
    acc[0] = fmaf((W), f0.x, acc[0]); acc[1] = fmaf((W), f0.y, acc[1]); \
    acc[2] = fmaf((W), f1.x, acc[2]); acc[3] = fmaf((W), f1.y, acc[3]); \
    acc[4] = fmaf((W), f2.x, acc[4]); acc[5] = fmaf((W), f2.y, acc[5]); \
    acc[6] = fmaf((W), f3.x, acc[6]); acc[7] = fmaf((W), f3.y, acc[7]); }

__global__ __launch_bounds__(256) void agg128h_k() {
    int warp = (blockIdx.x * blockDim.x + threadIdx.x) >> 5;
    int lane = threadIdx.x & 31;
    int half = lane >> 4, hl = lane & 15;
    int node = warp * 2 + half;
    if (node >= N_NODES) return;
    const uint4* H16 = (const uint4*)g_hA;   // 16 x 16B per node row
    int beg = g_rowptr[node], end = g_rowptr[node + 1];
    float di = g_dinv[node];

    float acc[8];
    {   // self loop
        uint4 u = __ldcg(&H16[(size_t)node * 16 + hl]);
        float2 f0 = __half22float2(*(const __half2*)&u.x);
        float2 f1 = __half22float2(*(const __half2*)&u.y);
        float2 f2 = __half22float2(*(const __half2*)&u.z);
        float2 f3 = __half22float2(*(const __half2*)&u.w);
        acc[0] = di * f0.x; acc[1] = di * f0.y;
        acc[2] = di * f1.x; acc[3] = di * f1.y;
        acc[4] = di * f2.x; acc[5] = di * f2.y;
        acc[6] = di * f3.x; acc[7] = di * f3.y;
    }

    int e = beg;
    for (; e + 3 < end; e += 4) {
        int2 c0 = g_cw[e], c1 = g_cw[e + 1], c2 = g_cw[e + 2], c3 = g_cw[e + 3];
        uint4 u0 = __ldcg(&H16[(size_t)c0.x * 16 + hl]);
        uint4 u1 = __ldcg(&H16[(size_t)c1.x * 16 + hl]);
        uint4 u2 = __ldcg(&H16[(size_t)c2.x * 16 + hl]);
        uint4 u3 = __ldcg(&H16[(size_t)c3.x * 16 + hl]);
        ACC8(u0, __int_as_float(c0.y))
        ACC8(u1, __int_as_float(c1.y))
        ACC8(u2, __int_as_float(c2.y))
        ACC8(u3, __int_as_float(c3.y))
    }
    for (; e < end; e++) {
        int2 cw = g_cw[e];
        uint4 u = __ldcg(&H16[(size_t)cw.x * 16 + hl]);
        ACC8(u, __int_as_float(cw.y))
    }

    uint4 o;
    __half2 h0 = __floats2half2_rn(di * acc[0], di * acc[1]);
    __half2 h1 = __floats2half2_rn(di * acc[2], di * acc[3]);
    __half2 h2 = __floats2half2_rn(di * acc[4], di * acc[5]);
    __half2 h3 = __floats2half2_rn(di * acc[6], di * acc[7]);
    o.x = *(unsigned*)&h0; o.y = *(unsigned*)&h1;
    o.z = *(unsigned*)&h2; o.w = *(unsigned*)&h3;
    ((uint4*)g_hagg)[(size_t)node * 16 + hl] = o;
}

// ---- fp16 MMA GEMM, K=32: g_hx32[N,32] @ g_hWp1 + bias, relu -> g_hA ----
__global__ __launch_bounds__(128) void gemm32_h(const float* __restrict__ bias) {
    __shared__ __half sA[64 * 40];             // pitch 40 halves (80B)
    int tid = threadIdx.x, lane = tid & 31, wid = tid >> 5;
    int base = blockIdx.x * 64;

    const uint4* A16 = (const uint4*)g_hx32;   // 4 x 8-half chunks per node
    for (int i = tid; i < 64 * 4; i += 128) {
        int row = i >> 2, q = i & 3;
        int node = base + row;
        uint4 v = (node < N_NODES) ? A16[(size_t)node * 4 + q]
                                   : make_uint4(0u, 0u, 0u, 0u);
        *(uint4*)&sA[row * 40 + q * 8] = v;
    }
    __syncthreads();

    int gid = lane >> 2, tig = lane & 3;
    int m0 = wid * 16;

    float c[16][4];
#pragma unroll
    for (int nt = 0; nt < 16; nt++)
#pragma unroll
        for (int j = 0; j < 4; j++) c[nt][j] = 0.0f;

#pragma unroll
    for (int kt = 0; kt < 2; kt++) {
        int k0 = kt * 16;
        unsigned a0 = *(const unsigned*)&sA[(m0 + gid) * 40 + k0 + 2 * tig];
        unsigned a1 = *(const unsigned*)&sA[(m0 + gid + 8) * 40 + k0 + 2 * tig];
        unsigned a2 = *(const unsigned*)&sA[(m0 + gid) * 40 + k0 + 2 * tig + 8];
        unsigned a3 = *(const unsigned*)&sA[(m0 + gid + 8) * 40 + k0 + 2 * tig + 8];
        const uint2* wrow = &g_hWp1[(kt * 128) * 4 + tig];
#pragma unroll
        for (int nt = 0; nt < 16; nt++) {
            uint2 b = wrow[(nt * 8 + gid) * 4];
            asm volatile(
                "mma.sync.aligned.m16n8k16.row.col.f32.f16.f16.f32 "
                "{%0,%1,%2,%3}, {%4,%5,%6,%7}, {%8,%9}, {%0,%1,%2,%3};"
                : "+f"(c[nt][0]), "+f"(c[nt][1]), "+f"(c[nt][2]), "+f"(c[nt][3])
                : "r"(a0), "r"(a1), "r"(a2), "r"(a3),
                  "r"(b.x), "r"(b.y));
        }
    }

    int row0 = base + m0 + gid;
    int row1 = row0 + 8;
#pragma unroll
    for (int nt = 0; nt < 16; nt++) {
        int n0 = nt * 8 + 2 * tig;
        float bx = bias[n0], by = bias[n0 + 1];
        if (row0 < N_NODES)
            *(__half2*)&g_hA[(size_t)row0 * HID + n0] =
                __floats2half2_rn(fmaxf(c[nt][0] + bx, 0.f), fmaxf(c[nt][1] + by, 0.f));
        if (row1 < N_NODES)
            *(__half2*)&g_hA[(size_t)row1 * HID + n0] =
                __floats2half2_rn(fmaxf(c[nt][2] + bx, 0.f), fmaxf(c[nt][3] + by, 0.f));
    }
}

// ---- fp16 MMA GEMM, K=128: g_hagg @ g_hWp[slot] + bias, relu -> g_hA ----
__global__ __launch_bounds__(128) void gemm128_h(const float* __restrict__ bias,
                                                 int slot) {
    __shared__ __half sA[64 * 136];            // pitch 136 halves (272B)
    int tid = threadIdx.x, lane = tid & 31, wid = tid >> 5;
    int base = blockIdx.x * 64;

    const uint4* A16 = (const uint4*)g_hagg;   // 16 x 8-half chunks per node
    for (int i = tid; i < 64 * 16; i += 128) {
        int row = i >> 4, q = i & 15;
        int node = base + row;
        uint4 v = (node < N_NODES) ? A16[(size_t)node * 16 + q]
                                   : make_uint4(0u, 0u, 0u, 0u);
        *(uint4*)&sA[row * 136 + q * 8] = v;
    }
    __syncthreads();

    int gid = lane >> 2, tig = lane & 3;
    int m0 = wid * 16;
    const uint2* Wp = g_hWp[slot];

    float c[16][4];
#pragma unroll
    for (int nt = 0; nt < 16; nt++)
#pragma unroll
        for (int j = 0; j < 4; j++) c[nt][j] = 0.0f;

#pragma unroll
    for (int kt = 0; kt < 8; kt++) {
        int k0 = kt * 16;
        unsigned a0 = *(const unsigned*)&sA[(m0 + gid) * 136 + k0 + 2 * tig];
        unsigned a1 = *(const unsigned*)&sA[(m0 + gid + 8) * 136 + k0 + 2 * tig];
        unsigned a2 = *(const unsigned*)&sA[(m0 + gid) * 136 + k0 + 2 * tig + 8];
        unsigned a3 = *(const unsigned*)&sA[(m0 + gid + 8) * 136 + k0 + 2 * tig + 8];
        const uint2* wrow = &Wp[(size_t)(kt * 128) * 4 + tig];
#pragma unroll
        for (int nt = 0; nt < 16; nt++) {
            uint2 b = wrow[(nt * 8 + gid) * 4];
            asm volatile(
                "mma.sync.aligned.m16n8k16.row.col.f32.f16.f16.f32 "
                "{%0,%1,%2,%3}, {%4,%5,%6,%7}, {%8,%9}, {%0,%1,%2,%3};"
                : "+f"(c[nt][0]), "+f"(c[nt][1]), "+f"(c[nt][2]), "+f"(c[nt][3])
                : "r"(a0), "r"(a1), "r"(a2), "r"(a3),
                  "r"(b.x), "r"(b.y));
        }
    }

    int row0 = base + m0 + gid;
    int row1 = row0 + 8;
#pragma unroll
    for (int nt = 0; nt < 16; nt++) {
        int n0 = nt * 8 + 2 * tig;
        float bx = bias[n0], by = bias[n0 + 1];
        if (row0 < N_NODES)
            *(__half2*)&g_hA[(size_t)row0 * HID + n0] =
                __floats2half2_rn(fmaxf(c[nt][0] + bx, 0.f), fmaxf(c[nt][1] + by, 0.f));
        if (row1 < N_NODES)
            *(__half2*)&g_hA[(size_t)row1 * HID + n0] =
                __floats2half2_rn(fmaxf(c[nt][2] + bx, 0.f), fmaxf(c[nt][3] + by, 0.f));
    }
}

// ---- fused mean-pool + head: block per graph ----
__global__ __launch_bounds__(128) void poolhead_k(const float* __restrict__ Wout,
                                                  const float* __restrict__ bout,
                                                  float* __restrict__ out) {
    __shared__ float sp[HID];
    int g = blockIdx.x;
    int c = threadIdx.x;
    int s = g_gstart[g], e = g_gstart[g + 1];
    float acc = 0.0f;
    for (int n = s; n < e; n++) acc += __half2float(g_hA[(size_t)n * HID + c]);
    sp[c] = acc / fmaxf((float)(e - s), 1.0f);
    __syncthreads();
    if (c < OUT_F) {
        float o = bout[c];
#pragma unroll 8
        for (int k = 0; k < HID; k++)
            o = fmaf(sp[k], Wout[k * OUT_F + c], o);
        out[g * OUT_F + c] = o;
    }
}

// ---------------- launch (kernel launches ONLY — graph-capture safe) ----------------
extern "C" void kernel_launch(void* const* d_in, const int* in_sizes, int n_in,
                              void* d_out, int out_size) {
    const float* x     = (const float*)d_in[0];
    const int*   ei    = (const int*)d_in[1];    // int32 (JAX x64 disabled)
    const int*   batch = (const int*)d_in[2];    // int32
    const float* W1 = (const float*)d_in[3];
    const float* b1 = (const float*)d_in[4];
    const float* W2 = (const float*)d_in[5];
    const float* b2 = (const float*)d_in[6];
    const float* W3 = (const float*)d_in[7];
    const float* b3 = (const float*)d_in[8];
    const float* Wout = (const float*)d_in[9];
    const float* bout = (const float*)d_in[10];
    float* out = (float*)d_out;

    const int NB = 256;
    int nblk_edges = (N_EDGES + NB - 1) / NB;
    int nblk_quarter = ((N_NODES + 3) / 4 * 32 + NB - 1) / NB;    // 4 nodes/warp
    int nblk_halfwarp = ((N_NODES + 1) / 2 * 32 + NB - 1) / NB;   // 2 nodes/warp
    int nblk_tc = (N_NODES + 63) / 64;

    // 1. histogram + x->fp16 conversion (+ lookback-state reset)
    hist_k<<<nblk_edges, NB>>>(ei, x);
    // 2. scan + dinv + bounds + weight packing (lookback)
    scanAll_k<<<NBLK_SCAN + NBLK_PACK, 1024>>>(batch, W1, W2, W3);
    // 3. CSR fill
    fill_k<<<nblk_edges, NB>>>(ei);
    // 4-5. layer 1 (quarter-warp gather on fp16 x)
    agg20q_k<<<nblk_quarter, NB>>>();
    gemm32_h<<<nblk_tc, 128>>>(b1);
    // 6-7. layer 2
    agg128h_k<<<nblk_halfwarp, NB>>>();
    gemm128_h<<<nblk_tc, 128>>>(b2, 0);
    // 8-9. layer 3
    agg128h_k<<<nblk_halfwarp, NB>>>();
    gemm128_h<<<nblk_tc, 128>>>(b3, 1);
    // 10. pool + head
    poolhead_k<<<N_GRAPHS, 128>>>(Wout, bout, out);
}